// round 2
// baseline (speedup 1.0000x reference)
#include <cuda_runtime.h>

#define NN 50000
#define EE 800000
#define GG 500
#define H 128
#define OUTC 10
#define AP 136   // padded A-tile row stride (floats), 16B aligned

// ---------------- device scratch (no allocations allowed) ----------------
__device__ float g_h[NN * H];      // node features (layer output)
__device__ float g_agg[NN * H];    // (1+eps)*h + neighbor sum (MLP input)
__device__ int   g_deg[NN];
__device__ int   g_off[NN + 1];
__device__ int   g_cursor[NN];
__device__ int   g_srcs[EE];       // CSR-by-dst neighbor source ids
__device__ float g_pool[GG * H];
__device__ float g_cnt[GG];

// ---------------- packed f32x2 helpers ----------------
#define PACK2(d, x, y) asm("mov.b64 %0, {%1, %2};" : "=l"(d) : "f"(x), "f"(y))
#define FMA2(acc, a, b) asm("fma.rn.f32x2 %0, %1, %2, %0;" : "+l"(acc) : "l"(a), "l"(b))
#define UNPACK2(x, y, d) asm("mov.b64 {%0, %1}, %2;" : "=f"(x), "=f"(y) : "l"(d))

// ---------------- CSR build ----------------
__global__ void zero_deg_kernel(int n) {
    int i = blockIdx.x * blockDim.x + threadIdx.x;
    if (i < n) g_deg[i] = 0;
}

__global__ void count_kernel(const int* __restrict__ dst, int e) {
    int i = blockIdx.x * blockDim.x + threadIdx.x;
    if (i < e) atomicAdd(&g_deg[dst[i]], 1);
}

__global__ void scan_kernel(int n) {
    __shared__ int part[1024];
    int t = threadIdx.x;
    int chunk = (n + 1023) >> 10;
    int start = t * chunk;
    int s = 0;
    for (int i = 0; i < chunk; i++) {
        int idx = start + i;
        if (idx < n) s += g_deg[idx];
    }
    part[t] = s;
    __syncthreads();
    for (int off = 1; off < 1024; off <<= 1) {
        int v = 0;
        if (t >= off) v = part[t - off];
        __syncthreads();
        part[t] += v;
        __syncthreads();
    }
    int base = (t == 0) ? 0 : part[t - 1];
    for (int i = 0; i < chunk; i++) {
        int idx = start + i;
        if (idx < n) {
            g_off[idx] = base;
            g_cursor[idx] = base;
            base += g_deg[idx];
        }
    }
    if (t == 1023) g_off[n] = part[1023];
}

__global__ void fill_kernel(const int* __restrict__ src, const int* __restrict__ dst, int e) {
    int i = blockIdx.x * blockDim.x + threadIdx.x;
    if (i < e) {
        int d = dst[i];
        int p = atomicAdd(&g_cursor[d], 1);
        g_srcs[p] = src[i];
    }
}

// ---------------- aggregation: agg[v] = (1+eps)*in[v] + sum_{u in N(v)} in[u] ----------------
// one warp per node; float4 per lane (128 floats per row)
__global__ void agg_kernel(const float* __restrict__ xext, int use_ext,
                           const float* __restrict__ eps, int n) {
    int gw = (blockIdx.x * blockDim.x + threadIdx.x) >> 5;
    int lane = threadIdx.x & 31;
    if (gw >= n) return;
    const float* in = use_ext ? xext : (const float*)g_h;
    const float4* in4 = (const float4*)in;
    float e = 1.0f + *eps;
    float4 a = in4[gw * 32 + lane];
    float4 acc;
    acc.x = a.x * e; acc.y = a.y * e; acc.z = a.z * e; acc.w = a.w * e;
    int s0 = g_off[gw], s1 = g_off[gw + 1];
    int i = s0;
    for (; i + 1 < s1; i += 2) {
        int sa = g_srcs[i], sb = g_srcs[i + 1];
        float4 va = in4[sa * 32 + lane];
        float4 vb = in4[sb * 32 + lane];
        acc.x += va.x; acc.y += va.y; acc.z += va.z; acc.w += va.w;
        acc.x += vb.x; acc.y += vb.y; acc.z += vb.z; acc.w += vb.w;
    }
    if (i < s1) {
        int sa = g_srcs[i];
        float4 va = in4[sa * 32 + lane];
        acc.x += va.x; acc.y += va.y; acc.z += va.z; acc.w += va.w;
    }
    ((float4*)g_agg)[gw * 32 + lane] = acc;
}

// ---------------- fused MLP: h = BN(relu(relu(agg@W1+b1)@W2+b2)) ----------------
__device__ __forceinline__ void gemm_tile(const float* __restrict__ sA,
                                          const float* __restrict__ sW,
                                          int tx, int ty,
                                          unsigned long long (&acc)[8][4]) {
    for (int kk = 0; kk < 128; kk += 4) {
        float4 a4[8];
#pragma unroll
        for (int r = 0; r < 8; r++)
            a4[r] = *(const float4*)&sA[(ty * 8 + r) * AP + kk];
#pragma unroll
        for (int q = 0; q < 4; q++) {
            int k = kk + q;
            float4 w0 = *(const float4*)&sW[k * 128 + tx * 8];
            float4 w1 = *(const float4*)&sW[k * 128 + tx * 8 + 4];
            unsigned long long wp[4];
            PACK2(wp[0], w0.x, w0.y);
            PACK2(wp[1], w0.z, w0.w);
            PACK2(wp[2], w1.x, w1.y);
            PACK2(wp[3], w1.z, w1.w);
#pragma unroll
            for (int r = 0; r < 8; r++) {
                float av = (q == 0) ? a4[r].x : (q == 1) ? a4[r].y : (q == 2) ? a4[r].z : a4[r].w;
                unsigned long long ap;
                PACK2(ap, av, av);
#pragma unroll
                for (int c = 0; c < 4; c++) FMA2(acc[r][c], ap, wp[c]);
            }
        }
    }
}

__global__ __launch_bounds__(256) void mlp_kernel(
    const float* __restrict__ W1, const float* __restrict__ b1,
    const float* __restrict__ W2, const float* __restrict__ b2,
    const float* __restrict__ gam, const float* __restrict__ bet,
    const float* __restrict__ rm, const float* __restrict__ rv,
    int nrows) {
    extern __shared__ float smem[];
    float* sW1 = smem;                  // 128*128
    float* sW2 = smem + 128 * 128;      // 128*128
    float* sA  = smem + 2 * 128 * 128;  // 128*AP
    int tid = threadIdx.x;
    int tx = tid & 15, ty = tid >> 4;
    int row0 = blockIdx.x * 128;

    // cooperative load of both weight matrices
    const float4* W14 = (const float4*)W1;
    const float4* W24 = (const float4*)W2;
    float4* sW14 = (float4*)sW1;
    float4* sW24 = (float4*)sW2;
    for (int i = tid; i < 128 * 32; i += 256) {
        sW14[i] = W14[i];
        sW24[i] = W24[i];
    }
    // load A tile (zero-pad out-of-range rows)
    const float4* A4 = (const float4*)g_agg;
    for (int i = tid; i < 128 * 32; i += 256) {
        int r = i >> 5, c4 = i & 31;
        int row = row0 + r;
        float4 v = (row < nrows) ? A4[row * 32 + c4] : make_float4(0.f, 0.f, 0.f, 0.f);
        *(float4*)&sA[r * AP + c4 * 4] = v;
    }
    __syncthreads();

    unsigned long long acc[8][4];
#pragma unroll
    for (int r = 0; r < 8; r++)
#pragma unroll
        for (int c = 0; c < 4; c++) acc[r][c] = 0ULL;

    gemm_tile(sA, sW1, tx, ty, acc);

    // bias + relu -> write h1 back into sA
    float4 b1a = *(const float4*)&b1[tx * 8];
    float4 b1b = *(const float4*)&b1[tx * 8 + 4];
    float bb1[8] = {b1a.x, b1a.y, b1a.z, b1a.w, b1b.x, b1b.y, b1b.z, b1b.w};
    __syncthreads();  // all GEMM1 reads of sA complete
#pragma unroll
    for (int r = 0; r < 8; r++) {
        float hv[8];
#pragma unroll
        for (int c = 0; c < 4; c++) UNPACK2(hv[2 * c], hv[2 * c + 1], acc[r][c]);
        float4 o0, o1;
        float t0 = hv[0] + bb1[0]; o0.x = t0 > 0.f ? t0 : 0.f;
        float t1 = hv[1] + bb1[1]; o0.y = t1 > 0.f ? t1 : 0.f;
        float t2 = hv[2] + bb1[2]; o0.z = t2 > 0.f ? t2 : 0.f;
        float t3 = hv[3] + bb1[3]; o0.w = t3 > 0.f ? t3 : 0.f;
        float t4 = hv[4] + bb1[4]; o1.x = t4 > 0.f ? t4 : 0.f;
        float t5 = hv[5] + bb1[5]; o1.y = t5 > 0.f ? t5 : 0.f;
        float t6 = hv[6] + bb1[6]; o1.z = t6 > 0.f ? t6 : 0.f;
        float t7 = hv[7] + bb1[7]; o1.w = t7 > 0.f ? t7 : 0.f;
        *(float4*)&sA[(ty * 8 + r) * AP + tx * 8] = o0;
        *(float4*)&sA[(ty * 8 + r) * AP + tx * 8 + 4] = o1;
    }
    __syncthreads();

#pragma unroll
    for (int r = 0; r < 8; r++)
#pragma unroll
        for (int c = 0; c < 4; c++) acc[r][c] = 0ULL;

    gemm_tile(sA, sW2, tx, ty, acc);

    // bias + relu + batchnorm(eval) -> global h
    float4 b2a = *(const float4*)&b2[tx * 8];
    float4 b2b = *(const float4*)&b2[tx * 8 + 4];
    float bb2[8] = {b2a.x, b2a.y, b2a.z, b2a.w, b2b.x, b2b.y, b2b.z, b2b.w};
    float4 ga = *(const float4*)&gam[tx * 8];
    float4 gb = *(const float4*)&gam[tx * 8 + 4];
    float4 ba = *(const float4*)&bet[tx * 8];
    float4 bb = *(const float4*)&bet[tx * 8 + 4];
    float4 ma = *(const float4*)&rm[tx * 8];
    float4 mb = *(const float4*)&rm[tx * 8 + 4];
    float4 va = *(const float4*)&rv[tx * 8];
    float4 vb = *(const float4*)&rv[tx * 8 + 4];
    float gg[8] = {ga.x, ga.y, ga.z, ga.w, gb.x, gb.y, gb.z, gb.w};
    float be[8] = {ba.x, ba.y, ba.z, ba.w, bb.x, bb.y, bb.z, bb.w};
    float mm[8] = {ma.x, ma.y, ma.z, ma.w, mb.x, mb.y, mb.z, mb.w};
    float vv[8] = {va.x, va.y, va.z, va.w, vb.x, vb.y, vb.z, vb.w};
    float sc[8], sf[8];
#pragma unroll
    for (int c = 0; c < 8; c++) {
        sc[c] = gg[c] * rsqrtf(vv[c] + 1e-5f);
        sf[c] = be[c] - mm[c] * sc[c];
    }
    float4* out4 = (float4*)g_h;
#pragma unroll
    for (int r = 0; r < 8; r++) {
        int row = row0 + ty * 8 + r;
        if (row >= nrows) continue;
        float hv[8];
#pragma unroll
        for (int c = 0; c < 4; c++) UNPACK2(hv[2 * c], hv[2 * c + 1], acc[r][c]);
        float o[8];
#pragma unroll
        for (int c = 0; c < 8; c++) {
            float t = hv[c] + bb2[c];
            t = t > 0.f ? t : 0.f;
            o[c] = t * sc[c] + sf[c];
        }
        float4 v0 = make_float4(o[0], o[1], o[2], o[3]);
        float4 v1 = make_float4(o[4], o[5], o[6], o[7]);
        out4[row * 32 + tx * 2] = v0;
        out4[row * 32 + tx * 2 + 1] = v1;
    }
}

// ---------------- pooling ----------------
__global__ void zero_pool_kernel() {
    int i = blockIdx.x * blockDim.x + threadIdx.x;
    if (i < GG * H) g_pool[i] = 0.f;
    if (i < GG) g_cnt[i] = 0.f;
}

__global__ void pool_kernel(const int* __restrict__ batch, int n) {
    int gw = (blockIdx.x * blockDim.x + threadIdx.x) >> 5;
    int lane = threadIdx.x & 31;
    if (gw >= n) return;
    int b = batch[gw];
    float4 v = ((const float4*)g_h)[gw * 32 + lane];
    float* base = &g_pool[b * H + lane * 4];
    atomicAdd(base + 0, v.x);
    atomicAdd(base + 1, v.y);
    atomicAdd(base + 2, v.z);
    atomicAdd(base + 3, v.w);
    if (lane == 0) atomicAdd(&g_cnt[b], 1.0f);
}

// ---------------- head: mean, lin1+relu, lin2, log_softmax ----------------
__global__ void head_kernel(const float* __restrict__ lin1W, const float* __restrict__ lin1b,
                            const float* __restrict__ lin2W, const float* __restrict__ lin2b,
                            float* __restrict__ out) {
    __shared__ float sh[H];
    __shared__ float tt[H];
    __shared__ float lg[OUTC];
    int g = blockIdx.x, j = threadIdx.x;
    float c = g_cnt[g];
    if (c < 1.0f) c = 1.0f;
    sh[j] = g_pool[g * H + j] / c;
    __syncthreads();
    float s = lin1b[j];
#pragma unroll 8
    for (int k = 0; k < H; k++) s += sh[k] * lin1W[k * H + j];
    tt[j] = s > 0.f ? s : 0.f;
    __syncthreads();
    if (j < OUTC) {
        float s2 = lin2b[j];
#pragma unroll 8
        for (int k = 0; k < H; k++) s2 += tt[k] * lin2W[k * OUTC + j];
        lg[j] = s2;
    }
    __syncthreads();
    if (j == 0) {
        float m = lg[0];
#pragma unroll
        for (int o = 1; o < OUTC; o++) m = lg[o] > m ? lg[o] : m;
        float se = 0.f;
#pragma unroll
        for (int o = 0; o < OUTC; o++) se += expf(lg[o] - m);
        float l = m + logf(se);
#pragma unroll
        for (int o = 0; o < OUTC; o++) out[g * OUTC + o] = lg[o] - l;
    }
}

// ---------------- launch ----------------
extern "C" void kernel_launch(void* const* d_in, const int* in_sizes, int n_in,
                              void* d_out, int out_size) {
    const float* x      = (const float*)d_in[0];
    const int*   ei     = (const int*)d_in[1];
    const int*   batch  = (const int*)d_in[2];
    const float* c1_W1  = (const float*)d_in[3];
    const float* c1_b1  = (const float*)d_in[4];
    const float* c1_W2  = (const float*)d_in[5];
    const float* c1_b2  = (const float*)d_in[6];
    const float* c1_g   = (const float*)d_in[7];
    const float* c1_be  = (const float*)d_in[8];
    const float* c1_rm  = (const float*)d_in[9];
    const float* c1_rv  = (const float*)d_in[10];
    const float* c1_eps = (const float*)d_in[11];
    const float* Ws1    = (const float*)d_in[12];
    const float* bs1    = (const float*)d_in[13];
    const float* Ws2    = (const float*)d_in[14];
    const float* bs2    = (const float*)d_in[15];
    const float* gs     = (const float*)d_in[16];
    const float* bes    = (const float*)d_in[17];
    const float* rms    = (const float*)d_in[18];
    const float* rvs    = (const float*)d_in[19];
    const float* epss   = (const float*)d_in[20];
    const float* lin1_W = (const float*)d_in[21];
    const float* lin1_b = (const float*)d_in[22];
    const float* lin2_W = (const float*)d_in[23];
    const float* lin2_b = (const float*)d_in[24];
    float* out = (float*)d_out;

    int n = in_sizes[0] / H;   // 50000
    int e = in_sizes[1] / 2;   // 800000

    int mlp_smem = (2 * 128 * 128 + 128 * AP) * (int)sizeof(float);
    cudaFuncSetAttribute(mlp_kernel, cudaFuncAttributeMaxDynamicSharedMemorySize, mlp_smem);

    const int* src = ei;
    const int* dst = ei + e;

    // ---- CSR build ----
    zero_deg_kernel<<<(n + 255) / 256, 256>>>(n);
    count_kernel<<<(e + 255) / 256, 256>>>(dst, e);
    scan_kernel<<<1, 1024>>>(n);
    fill_kernel<<<(e + 255) / 256, 256>>>(src, dst, e);

    int agg_blocks = (n * 32 + 255) / 256;
    int mlp_blocks = (n + 127) / 128;

    // ---- layer 1 ----
    agg_kernel<<<agg_blocks, 256>>>(x, 1, c1_eps, n);
    mlp_kernel<<<mlp_blocks, 256, mlp_smem>>>(c1_W1, c1_b1, c1_W2, c1_b2,
                                              c1_g, c1_be, c1_rm, c1_rv, n);
    // ---- layers 2..3 ----
    for (int i = 0; i < 2; i++) {
        agg_kernel<<<agg_blocks, 256>>>(x, 0, epss + i, n);
        mlp_kernel<<<mlp_blocks, 256, mlp_smem>>>(Ws1 + i * H * H, bs1 + i * H,
                                                  Ws2 + i * H * H, bs2 + i * H,
                                                  gs + i * H, bes + i * H,
                                                  rms + i * H, rvs + i * H, n);
    }

    // ---- pooling + head ----
    zero_pool_kernel<<<(GG * H + 255) / 256, 256>>>();
    pool_kernel<<<agg_blocks, 256>>>(batch, n);
    head_kernel<<<GG, H>>>(lin1_W, lin1_b, lin2_W, lin2_b, out);
}

// round 4
// speedup vs baseline: 1.4810x; 1.4810x over previous
#include <cuda_runtime.h>
#include <cuda_bf16.h>
#include <stdint.h>

#define NN 50000
#define EE 800000
#define GG 500
#define H 128
#define OUTC 10
#define KS 136                 // padded row stride in bf16 elems
#define SB 272                 // row stride bytes
#define IMG (128 * KS * 2)     // 34816 B per 128x128 bf16 image
#define DSM (6 * IMG)          // 208896 B dynamic smem

// ---------------- device scratch ----------------
__device__ float g_h[NN * H];
__device__ float g_agg[NN * H];
__device__ int   g_deg[NN];
__device__ int   g_off[NN + 1];
__device__ int   g_cursor[NN];
__device__ int   g_srcs[EE];
__device__ float g_pool[GG * H];
__device__ float g_cnt[GG];
__device__ __align__(16) __nv_bfloat16 g_wh[6 * 128 * KS];  // weight images (Wt[n][k]) hi
__device__ __align__(16) __nv_bfloat16 g_wl[6 * 128 * KS];  // lo

// ---------------- PTX helpers (base ISA only) ----------------
__device__ __forceinline__ uint32_t smem_u32(const void* p) {
    uint32_t a;
    asm("{ .reg .u64 t; cvta.to.shared.u64 t, %1; cvt.u32.u64 %0, t; }" : "=r"(a) : "l"(p));
    return a;
}
#define LDSM4(r0, r1, r2, r3, addr) \
    asm volatile("ldmatrix.sync.aligned.m8n8.x4.shared.b16 {%0,%1,%2,%3}, [%4];" \
                 : "=r"(r0), "=r"(r1), "=r"(r2), "=r"(r3) : "r"(addr))
#define MMA16816(d, a0, a1, a2, a3, b0, b1) \
    asm volatile("mma.sync.aligned.m16n8k16.row.col.f32.bf16.bf16.f32 " \
                 "{%0,%1,%2,%3}, {%4,%5,%6,%7}, {%8,%9}, {%0,%1,%2,%3};" \
                 : "+f"((d)[0]), "+f"((d)[1]), "+f"((d)[2]), "+f"((d)[3]) \
                 : "r"(a0), "r"(a1), "r"(a2), "r"(a3), "r"(b0), "r"(b1))

__device__ __forceinline__ void bf_split_store(float v0, float v1, char* hi, char* lo, unsigned boff) {
    __nv_bfloat162 h2 = __floats2bfloat162_rn(v0, v1);
    float2 hf = __bfloat1622float2(h2);
    __nv_bfloat162 l2 = __floats2bfloat162_rn(v0 - hf.x, v1 - hf.y);
    *(unsigned int*)(hi + boff) = *(unsigned int*)&h2;
    *(unsigned int*)(lo + boff) = *(unsigned int*)&l2;
}

// ---------------- CSR build ----------------
__global__ void zero_deg_kernel(int n) {
    int i = blockIdx.x * blockDim.x + threadIdx.x;
    if (i < n) g_deg[i] = 0;
}
__global__ void count_kernel(const int* __restrict__ dst, int e) {
    int i = blockIdx.x * blockDim.x + threadIdx.x;
    if (i < e) atomicAdd(&g_deg[dst[i]], 1);
}
__global__ void scan_kernel(int n) {
    __shared__ int part[1024];
    int t = threadIdx.x;
    int chunk = (n + 1023) >> 10;
    int start = t * chunk;
    int s = 0;
    for (int i = 0; i < chunk; i++) {
        int idx = start + i;
        if (idx < n) s += g_deg[idx];
    }
    part[t] = s;
    __syncthreads();
    for (int off = 1; off < 1024; off <<= 1) {
        int v = 0;
        if (t >= off) v = part[t - off];
        __syncthreads();
        part[t] += v;
        __syncthreads();
    }
    int base = (t == 0) ? 0 : part[t - 1];
    for (int i = 0; i < chunk; i++) {
        int idx = start + i;
        if (idx < n) {
            g_off[idx] = base;
            g_cursor[idx] = base;
            base += g_deg[idx];
        }
    }
    if (t == 1023) g_off[n] = part[1023];
}
__global__ void fill_kernel(const int* __restrict__ src, const int* __restrict__ dst, int e) {
    int i = blockIdx.x * blockDim.x + threadIdx.x;
    if (i < e) {
        int d = dst[i];
        int p = atomicAdd(&g_cursor[d], 1);
        g_srcs[p] = src[i];
    }
}

// ---------------- aggregation ----------------
__global__ void agg_kernel(const float* __restrict__ xext, int use_ext,
                           const float* __restrict__ eps, int n) {
    int gw = (blockIdx.x * blockDim.x + threadIdx.x) >> 5;
    int lane = threadIdx.x & 31;
    if (gw >= n) return;
    const float4* in4 = use_ext ? (const float4*)xext : (const float4*)g_h;
    float e = 1.0f + *eps;
    float4 a = in4[gw * 32 + lane];
    float4 acc;
    acc.x = a.x * e; acc.y = a.y * e; acc.z = a.z * e; acc.w = a.w * e;
    int s0 = g_off[gw], s1 = g_off[gw + 1];
    int i = s0;
    for (; i + 1 < s1; i += 2) {
        int sa = g_srcs[i], sb = g_srcs[i + 1];
        float4 va = in4[sa * 32 + lane];
        float4 vb = in4[sb * 32 + lane];
        acc.x += va.x; acc.y += va.y; acc.z += va.z; acc.w += va.w;
        acc.x += vb.x; acc.y += vb.y; acc.z += vb.z; acc.w += vb.w;
    }
    if (i < s1) {
        int sa = g_srcs[i];
        float4 va = in4[sa * 32 + lane];
        acc.x += va.x; acc.y += va.y; acc.z += va.z; acc.w += va.w;
    }
    ((float4*)g_agg)[gw * 32 + lane] = acc;
}

// ---------------- weight prep: Wt[n][k] bf16 hi/lo, padded stride ----------------
__global__ void wprep_kernel(const float* __restrict__ c1W1, const float* __restrict__ c1W2,
                             const float* __restrict__ Ws1, const float* __restrict__ Ws2) {
    int m = blockIdx.x >> 2;
    int rg = blockIdx.x & 3;
    const float* W;
    if (m == 0) W = c1W1;
    else if (m == 1) W = c1W2;
    else {
        int l = (m - 2) >> 1;
        W = ((m & 1) == 0) ? (Ws1 + l * H * H) : (Ws2 + l * H * H);
    }
    int tid = threadIdx.x;
    int nrow = rg * 32 + (tid >> 3);
    int kb = (tid & 7) * 16;
    __nv_bfloat16* oh = g_wh + m * 128 * KS;
    __nv_bfloat16* ol = g_wl + m * 128 * KS;
#pragma unroll
    for (int i = 0; i < 8; i++) {
        int k = kb + 2 * i;
        float v0 = W[k * H + nrow];
        float v1 = W[(k + 1) * H + nrow];
        __nv_bfloat162 h2 = __floats2bfloat162_rn(v0, v1);
        float2 hf = __bfloat1622float2(h2);
        __nv_bfloat162 l2 = __floats2bfloat162_rn(v0 - hf.x, v1 - hf.y);
        *(__nv_bfloat162*)(oh + nrow * KS + k) = h2;
        *(__nv_bfloat162*)(ol + nrow * KS + k) = l2;
    }
}

// ---------------- fused MLP on mma.sync (HMMA bf16, hi/lo split) ----------------
__global__ __launch_bounds__(256, 1) void mlp_mma_kernel(
    int w1i, int w2i,
    const float* __restrict__ b1, const float* __restrict__ b2,
    const float* __restrict__ gam, const float* __restrict__ bet,
    const float* __restrict__ rm, const float* __restrict__ rv,
    const int* __restrict__ batchv, int lastlayer, int n) {
    extern __shared__ char dsm[];
    __shared__ float s_b1[H], s_b2[H], s_sc[H], s_sf[H];

    char* AHI = dsm;
    char* ALO = dsm + IMG;
    char* W1H = dsm + 2 * IMG;
    char* W1L = dsm + 3 * IMG;
    char* W2H = dsm + 4 * IMG;
    char* W2L = dsm + 5 * IMG;

    int tid = threadIdx.x, wid = tid >> 5, lane = tid & 31;
    int wm = wid >> 1, wn = wid & 1;        // 4x2 warp grid; warp tile 32(m) x 64(n)
    int qg = lane >> 2, qt = lane & 3;      // quad group / thread

    if (tid < H) {
        s_b1[tid] = b1[tid];
        s_b2[tid] = b2[tid];
        float sc = gam[tid] * rsqrtf(rv[tid] + 1e-5f);
        s_sc[tid] = sc;
        s_sf[tid] = bet[tid] - rm[tid] * sc;
    }
    // weight image copies (global, already split+padded)
    {
        const uint4* s1 = (const uint4*)(g_wh + w1i * 128 * KS);
        const uint4* s2 = (const uint4*)(g_wl + w1i * 128 * KS);
        const uint4* s3 = (const uint4*)(g_wh + w2i * 128 * KS);
        const uint4* s4 = (const uint4*)(g_wl + w2i * 128 * KS);
        uint4* d1 = (uint4*)W1H; uint4* d2 = (uint4*)W1L;
        uint4* d3 = (uint4*)W2H; uint4* d4 = (uint4*)W2L;
        for (int j = tid; j < IMG / 16; j += 256) {
            d1[j] = s1[j]; d2[j] = s2[j]; d3[j] = s3[j]; d4[j] = s4[j];
        }
    }
    // build A hi/lo images from g_agg
    int row0 = blockIdx.x * 128;
    {
        int r = tid >> 1, cb0 = (tid & 1) * 64;
        int grow = row0 + r;
        const float4* A4 = (const float4*)g_agg;
#pragma unroll
        for (int i = 0; i < 16; i++) {
            int c = cb0 + i * 4;
            float4 v = (grow < n) ? A4[(size_t)grow * 32 + (c >> 2)]
                                  : make_float4(0.f, 0.f, 0.f, 0.f);
            unsigned boff = (unsigned)(r * SB + c * 2);
            bf_split_store(v.x, v.y, AHI, ALO, boff);
            bf_split_store(v.z, v.w, AHI, ALO, boff + 4);
        }
    }
    __syncthreads();

    // per-lane ldmatrix address offsets
    uint32_t aAHI = smem_u32(AHI), aALO = smem_u32(ALO);
    uint32_t aW1H = smem_u32(W1H), aW1L = smem_u32(W1L);
    uint32_t aW2H = smem_u32(W2H), aW2L = smem_u32(W2L);
    // A: lanes 0-15 -> rows, lanes 16-31 -> same rows +16B (k+8)
    uint32_t a_loff = (uint32_t)((wm * 32 + (lane & 15)) * SB + (lane >> 4) * 16);
    // B: rows n + (lane&7) + (lane>=16 ? 8:0); +16B if (lane>>3)&1
    uint32_t b_row = (uint32_t)((lane & 7) | ((lane & 16) >> 1));
    uint32_t b_loff = (uint32_t)((wn * 64) * SB) + b_row * SB + (((uint32_t)lane >> 3) & 1) * 16;

    float acc[2][8][4];

    for (int pass = 0; pass < 2; pass++) {
        uint32_t wHI = pass ? aW2H : aW1H;
        uint32_t wLO = pass ? aW2L : aW1L;
#pragma unroll
        for (int mf = 0; mf < 2; mf++)
#pragma unroll
            for (int nf = 0; nf < 8; nf++)
#pragma unroll
                for (int q = 0; q < 4; q++) acc[mf][nf][q] = 0.f;

#pragma unroll
        for (int prod = 0; prod < 3; prod++) {
            uint32_t ab = (prod == 1) ? aALO : aAHI;
            uint32_t wb = (prod == 2) ? wLO : wHI;
#pragma unroll
            for (int ks = 0; ks < 8; ks++) {
                uint32_t a0, a1, a2, a3, a4, a5, a6, a7;
                uint32_t abase = ab + a_loff + (uint32_t)(ks * 32);
                LDSM4(a0, a1, a2, a3, abase);
                LDSM4(a4, a5, a6, a7, abase + 16u * SB);
#pragma unroll
                for (int g2 = 0; g2 < 4; g2++) {
                    uint32_t b0, b1x, b2, b3;
                    uint32_t bbase = wb + b_loff + (uint32_t)(g2 * 16 * SB + ks * 32);
                    LDSM4(b0, b1x, b2, b3, bbase);
                    MMA16816(acc[0][2 * g2],     a0, a1, a2, a3, b0, b1x);
                    MMA16816(acc[0][2 * g2 + 1], a0, a1, a2, a3, b2, b3);
                    MMA16816(acc[1][2 * g2],     a4, a5, a6, a7, b0, b1x);
                    MMA16816(acc[1][2 * g2 + 1], a4, a5, a6, a7, b2, b3);
                }
            }
        }

        if (pass == 0) {
            // epilogue 1: bias + relu -> rebuild A hi/lo images
            __syncthreads();
#pragma unroll
            for (int mf = 0; mf < 2; mf++) {
                int rA = wm * 32 + mf * 16 + qg;
#pragma unroll
                for (int nf = 0; nf < 8; nf++) {
                    int c = wn * 64 + nf * 8 + 2 * qt;
                    float v0 = fmaxf(acc[mf][nf][0] + s_b1[c], 0.f);
                    float v1 = fmaxf(acc[mf][nf][1] + s_b1[c + 1], 0.f);
                    float v2 = fmaxf(acc[mf][nf][2] + s_b1[c], 0.f);
                    float v3 = fmaxf(acc[mf][nf][3] + s_b1[c + 1], 0.f);
                    bf_split_store(v0, v1, AHI, ALO, (unsigned)(rA * SB + c * 2));
                    bf_split_store(v2, v3, AHI, ALO, (unsigned)((rA + 8) * SB + c * 2));
                }
            }
            __syncthreads();
        }
    }

    // epilogue 2: bias + relu + BN -> g_h (or atomic pool on last layer)
#pragma unroll
    for (int mf = 0; mf < 2; mf++) {
        int rA = wm * 32 + mf * 16 + qg;
        int growA = row0 + rA, growB = growA + 8;
#pragma unroll
        for (int nf = 0; nf < 8; nf++) {
            int c = wn * 64 + nf * 8 + 2 * qt;
            float o0 = fmaxf(acc[mf][nf][0] + s_b2[c], 0.f)     * s_sc[c]     + s_sf[c];
            float o1 = fmaxf(acc[mf][nf][1] + s_b2[c + 1], 0.f) * s_sc[c + 1] + s_sf[c + 1];
            float o2 = fmaxf(acc[mf][nf][2] + s_b2[c], 0.f)     * s_sc[c]     + s_sf[c];
            float o3 = fmaxf(acc[mf][nf][3] + s_b2[c + 1], 0.f) * s_sc[c + 1] + s_sf[c + 1];
            if (!lastlayer) {
                if (growA < n) *(float2*)&g_h[(size_t)growA * H + c] = make_float2(o0, o1);
                if (growB < n) *(float2*)&g_h[(size_t)growB * H + c] = make_float2(o2, o3);
            } else {
                if (growA < n) {
                    float* pp = g_pool + (size_t)batchv[growA] * H + c;
                    atomicAdd(pp, o0);
                    atomicAdd(pp + 1, o1);
                }
                if (growB < n) {
                    float* pp = g_pool + (size_t)batchv[growB] * H + c;
                    atomicAdd(pp, o2);
                    atomicAdd(pp + 1, o3);
                }
            }
        }
    }
}

// ---------------- pooling setup ----------------
__global__ void zero_pool_kernel() {
    int i = blockIdx.x * blockDim.x + threadIdx.x;
    if (i < GG * H) g_pool[i] = 0.f;
    if (i < GG) g_cnt[i] = 0.f;
}
__global__ void cnt_kernel(const int* __restrict__ batch, int n) {
    int i = blockIdx.x * blockDim.x + threadIdx.x;
    if (i < n) atomicAdd(&g_cnt[batch[i]], 1.0f);
}

// ---------------- head ----------------
__global__ void head_kernel(const float* __restrict__ lin1W, const float* __restrict__ lin1b,
                            const float* __restrict__ lin2W, const float* __restrict__ lin2b,
                            float* __restrict__ out) {
    __shared__ float sh[H];
    __shared__ float tt[H];
    __shared__ float lg[OUTC];
    int g = blockIdx.x, j = threadIdx.x;
    float c = g_cnt[g];
    if (c < 1.0f) c = 1.0f;
    sh[j] = g_pool[g * H + j] / c;
    __syncthreads();
    float s = lin1b[j];
#pragma unroll 8
    for (int k = 0; k < H; k++) s += sh[k] * lin1W[k * H + j];
    tt[j] = s > 0.f ? s : 0.f;
    __syncthreads();
    if (j < OUTC) {
        float s2 = lin2b[j];
#pragma unroll 8
        for (int k = 0; k < H; k++) s2 += tt[k] * lin2W[k * OUTC + j];
        lg[j] = s2;
    }
    __syncthreads();
    if (j == 0) {
        float m = lg[0];
#pragma unroll
        for (int o = 1; o < OUTC; o++) m = lg[o] > m ? lg[o] : m;
        float se = 0.f;
#pragma unroll
        for (int o = 0; o < OUTC; o++) se += expf(lg[o] - m);
        float l = m + logf(se);
#pragma unroll
        for (int o = 0; o < OUTC; o++) out[g * OUTC + o] = lg[o] - l;
    }
}

// ---------------- launch ----------------
extern "C" void kernel_launch(void* const* d_in, const int* in_sizes, int n_in,
                              void* d_out, int out_size) {
    const float* x      = (const float*)d_in[0];
    const int*   ei     = (const int*)d_in[1];
    const int*   batch  = (const int*)d_in[2];
    const float* c1_W1  = (const float*)d_in[3];
    const float* c1_b1  = (const float*)d_in[4];
    const float* c1_W2  = (const float*)d_in[5];
    const float* c1_b2  = (const float*)d_in[6];
    const float* c1_g   = (const float*)d_in[7];
    const float* c1_be  = (const float*)d_in[8];
    const float* c1_rm  = (const float*)d_in[9];
    const float* c1_rv  = (const float*)d_in[10];
    const float* c1_eps = (const float*)d_in[11];
    const float* Ws1    = (const float*)d_in[12];
    const float* bs1    = (const float*)d_in[13];
    const float* Ws2    = (const float*)d_in[14];
    const float* bs2    = (const float*)d_in[15];
    const float* gs     = (const float*)d_in[16];
    const float* bes    = (const float*)d_in[17];
    const float* rms    = (const float*)d_in[18];
    const float* rvs    = (const float*)d_in[19];
    const float* epss   = (const float*)d_in[20];
    const float* lin1_W = (const float*)d_in[21];
    const float* lin1_b = (const float*)d_in[22];
    const float* lin2_W = (const float*)d_in[23];
    const float* lin2_b = (const float*)d_in[24];
    float* out = (float*)d_out;

    int n = in_sizes[0] / H;
    int e = in_sizes[1] / 2;

    cudaFuncSetAttribute(mlp_mma_kernel, cudaFuncAttributeMaxDynamicSharedMemorySize, DSM);

    const int* src = ei;
    const int* dst = ei + e;

    // CSR build
    zero_deg_kernel<<<(n + 255) / 256, 256>>>(n);
    count_kernel<<<(e + 255) / 256, 256>>>(dst, e);
    scan_kernel<<<1, 1024>>>(n);
    fill_kernel<<<(e + 255) / 256, 256>>>(src, dst, e);

    // pool setup + weight images
    zero_pool_kernel<<<(GG * H + 255) / 256, 256>>>();
    cnt_kernel<<<(n + 255) / 256, 256>>>(batch, n);
    wprep_kernel<<<24, 256>>>(c1_W1, c1_W2, Ws1, Ws2);

    int agg_blocks = (n * 32 + 255) / 256;
    int mlp_blocks = (n + 127) / 128;

    // layer 1
    agg_kernel<<<agg_blocks, 256>>>(x, 1, c1_eps, n);
    mlp_mma_kernel<<<mlp_blocks, 256, DSM>>>(0, 1, c1_b1, c1_b2,
                                             c1_g, c1_be, c1_rm, c1_rv,
                                             batch, 0, n);
    // layer 2
    agg_kernel<<<agg_blocks, 256>>>(x, 0, epss + 0, n);
    mlp_mma_kernel<<<mlp_blocks, 256, DSM>>>(2, 3, bs1, bs2,
                                             gs, bes, rms, rvs,
                                             batch, 0, n);
    // layer 3 (pools directly)
    agg_kernel<<<agg_blocks, 256>>>(x, 0, epss + 1, n);
    mlp_mma_kernel<<<mlp_blocks, 256, DSM>>>(4, 5, bs1 + H, bs2 + H,
                                             gs + H, bes + H, rms + H, rvs + H,
                                             batch, 1, n);

    head_kernel<<<GG, H>>>(lin1_W, lin1_b, lin2_W, lin2_b, out);
}

// round 5
// speedup vs baseline: 1.5743x; 1.0630x over previous
#include <cuda_runtime.h>
#include <cuda_bf16.h>
#include <cuda_fp16.h>
#include <stdint.h>

#define NN 50000
#define EE 800000
#define GG 500
#define H 128
#define OUTC 10
#define KS 136                 // padded row stride in bf16 elems
#define SB 272                 // row stride bytes
#define IMG (128 * KS * 2)     // 34816 B per 128x128 bf16 image
#define DSM (6 * IMG)          // 208896 B dynamic smem

// ---------------- device scratch ----------------
__device__ __align__(16) __half g_hf[NN * H];   // node features (f16)
__device__ float g_agg[NN * H];                 // f32 agg sums (MLP input)
__device__ int   g_deg[NN];
__device__ int   g_off[NN + 1];
__device__ int   g_cursor[NN];
__device__ int   g_srcs[EE];
__device__ float g_pool[GG * H];
__device__ float g_cnt[GG];
__device__ __align__(16) __nv_bfloat16 g_wh[6 * 128 * KS];  // weight images (Wt[n][k]) hi
__device__ __align__(16) __nv_bfloat16 g_wl[6 * 128 * KS];  // lo

// ---------------- PTX helpers (base ISA only) ----------------
__device__ __forceinline__ uint32_t smem_u32(const void* p) {
    uint32_t a;
    asm("{ .reg .u64 t; cvta.to.shared.u64 t, %1; cvt.u32.u64 %0, t; }" : "=r"(a) : "l"(p));
    return a;
}
#define LDSM4(r0, r1, r2, r3, addr) \
    asm volatile("ldmatrix.sync.aligned.m8n8.x4.shared.b16 {%0,%1,%2,%3}, [%4];" \
                 : "=r"(r0), "=r"(r1), "=r"(r2), "=r"(r3) : "r"(addr))
#define MMA16816(d, a0, a1, a2, a3, b0, b1) \
    asm volatile("mma.sync.aligned.m16n8k16.row.col.f32.bf16.bf16.f32 " \
                 "{%0,%1,%2,%3}, {%4,%5,%6,%7}, {%8,%9}, {%0,%1,%2,%3};" \
                 : "+f"((d)[0]), "+f"((d)[1]), "+f"((d)[2]), "+f"((d)[3]) \
                 : "r"(a0), "r"(a1), "r"(a2), "r"(a3), "r"(b0), "r"(b1))

__device__ __forceinline__ void bf_split_store(float v0, float v1, char* hi, char* lo, unsigned boff) {
    __nv_bfloat162 h2 = __floats2bfloat162_rn(v0, v1);
    float2 hf = __bfloat1622float2(h2);
    __nv_bfloat162 l2 = __floats2bfloat162_rn(v0 - hf.x, v1 - hf.y);
    *(unsigned int*)(hi + boff) = *(unsigned int*)&h2;
    *(unsigned int*)(lo + boff) = *(unsigned int*)&l2;
}

// ---------------- setup: zero + counts ----------------
__global__ void zero_kernel(int n) {
    int i = blockIdx.x * blockDim.x + threadIdx.x;
    if (i < n) g_deg[i] = 0;
    if (i < GG * H) g_pool[i] = 0.f;
    if (i < GG) g_cnt[i] = 0.f;
}
__global__ void count_kernel(const int* __restrict__ dst, const int* __restrict__ batch,
                             int e, int n) {
    int i = blockIdx.x * blockDim.x + threadIdx.x;
    if (i < e) atomicAdd(&g_deg[dst[i]], 1);
    if (i < n) atomicAdd(&g_cnt[batch[i]], 1.0f);
}
__global__ void scan_kernel(int n) {
    __shared__ int part[1024];
    int t = threadIdx.x;
    int chunk = (n + 1023) >> 10;
    int start = t * chunk;
    int s = 0;
    for (int i = 0; i < chunk; i++) {
        int idx = start + i;
        if (idx < n) s += g_deg[idx];
    }
    part[t] = s;
    __syncthreads();
    for (int off = 1; off < 1024; off <<= 1) {
        int v = 0;
        if (t >= off) v = part[t - off];
        __syncthreads();
        part[t] += v;
        __syncthreads();
    }
    int base = (t == 0) ? 0 : part[t - 1];
    for (int i = 0; i < chunk; i++) {
        int idx = start + i;
        if (idx < n) {
            g_off[idx] = base;
            g_cursor[idx] = base;
            base += g_deg[idx];
        }
    }
    if (t == 1023) g_off[n] = part[1023];
}
__global__ void fill_kernel(const int* __restrict__ src, const int* __restrict__ dst, int e) {
    int i = blockIdx.x * blockDim.x + threadIdx.x;
    if (i < e) {
        int d = dst[i];
        int p = atomicAdd(&g_cursor[d], 1);
        g_srcs[p] = src[i];
    }
}

// ---------------- x -> f16 convert ----------------
__global__ void xconv_kernel(const float* __restrict__ x, int total4) {
    int i = blockIdx.x * blockDim.x + threadIdx.x;
    if (i < total4) {
        float4 v = ((const float4*)x)[i];
        __half2 h0 = __floats2half2_rn(v.x, v.y);
        __half2 h1 = __floats2half2_rn(v.z, v.w);
        uint2 o;
        o.x = *(unsigned int*)&h0;
        o.y = *(unsigned int*)&h1;
        ((uint2*)g_hf)[i] = o;
    }
}

// ---------------- aggregation: f16 gather, f32 accumulate ----------------
__global__ void agg_kernel(const float* __restrict__ eps, int n) {
    int gw = (blockIdx.x * blockDim.x + threadIdx.x) >> 5;
    int lane = threadIdx.x & 31;
    if (gw >= n) return;
    const uint2* in2 = (const uint2*)g_hf;   // 4 halfs per lane, 32 lanes per row
    float e = 1.0f + *eps;
    uint2 sv = in2[(size_t)gw * 32 + lane];
    float2 f01 = __half22float2(*(__half2*)&sv.x);
    float2 f23 = __half22float2(*(__half2*)&sv.y);
    float4 acc;
    acc.x = f01.x * e; acc.y = f01.y * e; acc.z = f23.x * e; acc.w = f23.y * e;
    int s0 = g_off[gw], s1 = g_off[gw + 1];
    int i = s0;
    for (; i + 1 < s1; i += 2) {
        uint2 va = in2[(size_t)g_srcs[i] * 32 + lane];
        uint2 vb = in2[(size_t)g_srcs[i + 1] * 32 + lane];
        float2 a01 = __half22float2(*(__half2*)&va.x);
        float2 a23 = __half22float2(*(__half2*)&va.y);
        float2 b01 = __half22float2(*(__half2*)&vb.x);
        float2 b23 = __half22float2(*(__half2*)&vb.y);
        acc.x += a01.x + b01.x;
        acc.y += a01.y + b01.y;
        acc.z += a23.x + b23.x;
        acc.w += a23.y + b23.y;
    }
    if (i < s1) {
        uint2 va = in2[(size_t)g_srcs[i] * 32 + lane];
        float2 a01 = __half22float2(*(__half2*)&va.x);
        float2 a23 = __half22float2(*(__half2*)&va.y);
        acc.x += a01.x; acc.y += a01.y; acc.z += a23.x; acc.w += a23.y;
    }
    ((float4*)g_agg)[(size_t)gw * 32 + lane] = acc;
}

// ---------------- weight prep: Wt[n][k] bf16 hi/lo, padded stride ----------------
__global__ void wprep_kernel(const float* __restrict__ c1W1, const float* __restrict__ c1W2,
                             const float* __restrict__ Ws1, const float* __restrict__ Ws2) {
    int m = blockIdx.x >> 2;
    int rg = blockIdx.x & 3;
    const float* W;
    if (m == 0) W = c1W1;
    else if (m == 1) W = c1W2;
    else {
        int l = (m - 2) >> 1;
        W = ((m & 1) == 0) ? (Ws1 + l * H * H) : (Ws2 + l * H * H);
    }
    int tid = threadIdx.x;
    int nrow = rg * 32 + (tid >> 3);
    int kb = (tid & 7) * 16;
    __nv_bfloat16* oh = g_wh + m * 128 * KS;
    __nv_bfloat16* ol = g_wl + m * 128 * KS;
#pragma unroll
    for (int i = 0; i < 8; i++) {
        int k = kb + 2 * i;
        float v0 = W[k * H + nrow];
        float v1 = W[(k + 1) * H + nrow];
        __nv_bfloat162 h2 = __floats2bfloat162_rn(v0, v1);
        float2 hf = __bfloat1622float2(h2);
        __nv_bfloat162 l2 = __floats2bfloat162_rn(v0 - hf.x, v1 - hf.y);
        *(__nv_bfloat162*)(oh + nrow * KS + k) = h2;
        *(__nv_bfloat162*)(ol + nrow * KS + k) = l2;
    }
}

// ---------------- fused MLP on mma.sync (HMMA bf16, hi/lo split) ----------------
__global__ __launch_bounds__(256, 1) void mlp_mma_kernel(
    int w1i, int w2i,
    const float* __restrict__ b1, const float* __restrict__ b2,
    const float* __restrict__ gam, const float* __restrict__ bet,
    const float* __restrict__ rm, const float* __restrict__ rv,
    const int* __restrict__ batchv, int lastlayer, int n) {
    extern __shared__ char dsm[];
    __shared__ float s_b1[H], s_b2[H], s_sc[H], s_sf[H];

    char* AHI = dsm;
    char* ALO = dsm + IMG;
    char* W1H = dsm + 2 * IMG;
    char* W1L = dsm + 3 * IMG;
    char* W2H = dsm + 4 * IMG;
    char* W2L = dsm + 5 * IMG;

    int tid = threadIdx.x, wid = tid >> 5, lane = tid & 31;
    int wm = wid >> 1, wn = wid & 1;        // 4x2 warp grid; warp tile 32(m) x 64(n)
    int qg = lane >> 2, qt = lane & 3;      // quad group / thread

    if (tid < H) {
        s_b1[tid] = b1[tid];
        s_b2[tid] = b2[tid];
        float sc = gam[tid] * rsqrtf(rv[tid] + 1e-5f);
        s_sc[tid] = sc;
        s_sf[tid] = bet[tid] - rm[tid] * sc;
    }
    // weight image copies (global, already split+padded)
    {
        const uint4* s1 = (const uint4*)(g_wh + w1i * 128 * KS);
        const uint4* s2 = (const uint4*)(g_wl + w1i * 128 * KS);
        const uint4* s3 = (const uint4*)(g_wh + w2i * 128 * KS);
        const uint4* s4 = (const uint4*)(g_wl + w2i * 128 * KS);
        uint4* d1 = (uint4*)W1H; uint4* d2 = (uint4*)W1L;
        uint4* d3 = (uint4*)W2H; uint4* d4 = (uint4*)W2L;
        for (int j = tid; j < IMG / 16; j += 256) {
            d1[j] = s1[j]; d2[j] = s2[j]; d3[j] = s3[j]; d4[j] = s4[j];
        }
    }
    // build A hi/lo images from g_agg
    int row0 = blockIdx.x * 128;
    {
        int r = tid >> 1, cb0 = (tid & 1) * 64;
        int grow = row0 + r;
        const float4* A4 = (const float4*)g_agg;
#pragma unroll
        for (int i = 0; i < 16; i++) {
            int c = cb0 + i * 4;
            float4 v = (grow < n) ? A4[(size_t)grow * 32 + (c >> 2)]
                                  : make_float4(0.f, 0.f, 0.f, 0.f);
            unsigned boff = (unsigned)(r * SB + c * 2);
            bf_split_store(v.x, v.y, AHI, ALO, boff);
            bf_split_store(v.z, v.w, AHI, ALO, boff + 4);
        }
    }
    __syncthreads();

    // per-lane ldmatrix address offsets
    uint32_t aAHI = smem_u32(AHI), aALO = smem_u32(ALO);
    uint32_t aW1H = smem_u32(W1H), aW1L = smem_u32(W1L);
    uint32_t aW2H = smem_u32(W2H), aW2L = smem_u32(W2L);
    uint32_t a_loff = (uint32_t)((wm * 32 + (lane & 15)) * SB + (lane >> 4) * 16);
    uint32_t b_row = (uint32_t)((lane & 7) | ((lane & 16) >> 1));
    uint32_t b_loff = (uint32_t)((wn * 64) * SB) + b_row * SB + (((uint32_t)lane >> 3) & 1) * 16;

    float acc[2][8][4];

    for (int pass = 0; pass < 2; pass++) {
        uint32_t wHI = pass ? aW2H : aW1H;
        uint32_t wLO = pass ? aW2L : aW1L;
#pragma unroll
        for (int mf = 0; mf < 2; mf++)
#pragma unroll
            for (int nf = 0; nf < 8; nf++)
#pragma unroll
                for (int q = 0; q < 4; q++) acc[mf][nf][q] = 0.f;

#pragma unroll
        for (int prod = 0; prod < 3; prod++) {
            uint32_t ab = (prod == 1) ? aALO : aAHI;
            uint32_t wb = (prod == 2) ? wLO : wHI;
#pragma unroll
            for (int ks = 0; ks < 8; ks++) {
                uint32_t a0, a1, a2, a3, a4, a5, a6, a7;
                uint32_t abase = ab + a_loff + (uint32_t)(ks * 32);
                LDSM4(a0, a1, a2, a3, abase);
                LDSM4(a4, a5, a6, a7, abase + 16u * SB);
#pragma unroll
                for (int g2 = 0; g2 < 4; g2++) {
                    uint32_t b0, b1x, b2, b3;
                    uint32_t bbase = wb + b_loff + (uint32_t)(g2 * 16 * SB + ks * 32);
                    LDSM4(b0, b1x, b2, b3, bbase);
                    MMA16816(acc[0][2 * g2],     a0, a1, a2, a3, b0, b1x);
                    MMA16816(acc[0][2 * g2 + 1], a0, a1, a2, a3, b2, b3);
                    MMA16816(acc[1][2 * g2],     a4, a5, a6, a7, b0, b1x);
                    MMA16816(acc[1][2 * g2 + 1], a4, a5, a6, a7, b2, b3);
                }
            }
        }

        if (pass == 0) {
            // epilogue 1: bias + relu -> rebuild A hi/lo images
            __syncthreads();
#pragma unroll
            for (int mf = 0; mf < 2; mf++) {
                int rA = wm * 32 + mf * 16 + qg;
#pragma unroll
                for (int nf = 0; nf < 8; nf++) {
                    int c = wn * 64 + nf * 8 + 2 * qt;
                    float v0 = fmaxf(acc[mf][nf][0] + s_b1[c], 0.f);
                    float v1 = fmaxf(acc[mf][nf][1] + s_b1[c + 1], 0.f);
                    float v2 = fmaxf(acc[mf][nf][2] + s_b1[c], 0.f);
                    float v3 = fmaxf(acc[mf][nf][3] + s_b1[c + 1], 0.f);
                    bf_split_store(v0, v1, AHI, ALO, (unsigned)(rA * SB + c * 2));
                    bf_split_store(v2, v3, AHI, ALO, (unsigned)((rA + 8) * SB + c * 2));
                }
            }
            __syncthreads();
        }
    }

    // epilogue 2: bias + relu + BN -> g_hf f16 (or atomic pool on last layer)
#pragma unroll
    for (int mf = 0; mf < 2; mf++) {
        int rA = wm * 32 + mf * 16 + qg;
        int growA = row0 + rA, growB = growA + 8;
#pragma unroll
        for (int nf = 0; nf < 8; nf++) {
            int c = wn * 64 + nf * 8 + 2 * qt;
            float o0 = fmaxf(acc[mf][nf][0] + s_b2[c], 0.f)     * s_sc[c]     + s_sf[c];
            float o1 = fmaxf(acc[mf][nf][1] + s_b2[c + 1], 0.f) * s_sc[c + 1] + s_sf[c + 1];
            float o2 = fmaxf(acc[mf][nf][2] + s_b2[c], 0.f)     * s_sc[c]     + s_sf[c];
            float o3 = fmaxf(acc[mf][nf][3] + s_b2[c + 1], 0.f) * s_sc[c + 1] + s_sf[c + 1];
            if (!lastlayer) {
                if (growA < n) *(__half2*)&g_hf[(size_t)growA * H + c] = __floats2half2_rn(o0, o1);
                if (growB < n) *(__half2*)&g_hf[(size_t)growB * H + c] = __floats2half2_rn(o2, o3);
            } else {
                if (growA < n) {
                    float* pp = g_pool + (size_t)batchv[growA] * H + c;
                    atomicAdd(pp, o0);
                    atomicAdd(pp + 1, o1);
                }
                if (growB < n) {
                    float* pp = g_pool + (size_t)batchv[growB] * H + c;
                    atomicAdd(pp, o2);
                    atomicAdd(pp + 1, o3);
                }
            }
        }
    }
}

// ---------------- head ----------------
__global__ void head_kernel(const float* __restrict__ lin1W, const float* __restrict__ lin1b,
                            const float* __restrict__ lin2W, const float* __restrict__ lin2b,
                            float* __restrict__ out) {
    __shared__ float sh[H];
    __shared__ float tt[H];
    __shared__ float lg[OUTC];
    int g = blockIdx.x, j = threadIdx.x;
    float c = g_cnt[g];
    if (c < 1.0f) c = 1.0f;
    sh[j] = g_pool[g * H + j] / c;
    __syncthreads();
    float s = lin1b[j];
#pragma unroll 8
    for (int k = 0; k < H; k++) s += sh[k] * lin1W[k * H + j];
    tt[j] = s > 0.f ? s : 0.f;
    __syncthreads();
    if (j < OUTC) {
        float s2 = lin2b[j];
#pragma unroll 8
        for (int k = 0; k < H; k++) s2 += tt[k] * lin2W[k * OUTC + j];
        lg[j] = s2;
    }
    __syncthreads();
    if (j == 0) {
        float m = lg[0];
#pragma unroll
        for (int o = 1; o < OUTC; o++) m = lg[o] > m ? lg[o] : m;
        float se = 0.f;
#pragma unroll
        for (int o = 0; o < OUTC; o++) se += expf(lg[o] - m);
        float l = m + logf(se);
#pragma unroll
        for (int o = 0; o < OUTC; o++) out[g * OUTC + o] = lg[o] - l;
    }
}

// ---------------- launch ----------------
extern "C" void kernel_launch(void* const* d_in, const int* in_sizes, int n_in,
                              void* d_out, int out_size) {
    const float* x      = (const float*)d_in[0];
    const int*   ei     = (const int*)d_in[1];
    const int*   batch  = (const int*)d_in[2];
    const float* c1_W1  = (const float*)d_in[3];
    const float* c1_b1  = (const float*)d_in[4];
    const float* c1_W2  = (const float*)d_in[5];
    const float* c1_b2  = (const float*)d_in[6];
    const float* c1_g   = (const float*)d_in[7];
    const float* c1_be  = (const float*)d_in[8];
    const float* c1_rm  = (const float*)d_in[9];
    const float* c1_rv  = (const float*)d_in[10];
    const float* c1_eps = (const float*)d_in[11];
    const float* Ws1    = (const float*)d_in[12];
    const float* bs1    = (const float*)d_in[13];
    const float* Ws2    = (const float*)d_in[14];
    const float* bs2    = (const float*)d_in[15];
    const float* gs     = (const float*)d_in[16];
    const float* bes    = (const float*)d_in[17];
    const float* rms    = (const float*)d_in[18];
    const float* rvs    = (const float*)d_in[19];
    const float* epss   = (const float*)d_in[20];
    const float* lin1_W = (const float*)d_in[21];
    const float* lin1_b = (const float*)d_in[22];
    const float* lin2_W = (const float*)d_in[23];
    const float* lin2_b = (const float*)d_in[24];
    float* out = (float*)d_out;

    int n = in_sizes[0] / H;
    int e = in_sizes[1] / 2;

    cudaFuncSetAttribute(mlp_mma_kernel, cudaFuncAttributeMaxDynamicSharedMemorySize, DSM);

    const int* src = ei;
    const int* dst = ei + e;

    // setup + CSR build
    zero_kernel<<<(GG * H + 255) / 256, 256>>>(n);          // covers n<=GG*H? no: n=50000 < 64000 ok
    count_kernel<<<(e + 255) / 256, 256>>>(dst, batch, e, n);
    scan_kernel<<<1, 1024>>>(n);
    fill_kernel<<<(e + 255) / 256, 256>>>(src, dst, e);
    wprep_kernel<<<24, 256>>>(c1_W1, c1_W2, Ws1, Ws2);
    xconv_kernel<<<(n * H / 4 + 255) / 256, 256>>>(x, n * H / 4);

    int agg_blocks = (n * 32 + 255) / 256;
    int mlp_blocks = (n + 127) / 128;

    // layer 1
    agg_kernel<<<agg_blocks, 256>>>(c1_eps, n);
    mlp_mma_kernel<<<mlp_blocks, 256, DSM>>>(0, 1, c1_b1, c1_b2,
                                             c1_g, c1_be, c1_rm, c1_rv,
                                             batch, 0, n);
    // layer 2
    agg_kernel<<<agg_blocks, 256>>>(epss + 0, n);
    mlp_mma_kernel<<<mlp_blocks, 256, DSM>>>(2, 3, bs1, bs2,
                                             gs, bes, rms, rvs,
                                             batch, 0, n);
    // layer 3 (pools directly)
    agg_kernel<<<agg_blocks, 256>>>(epss + 1, n);
    mlp_mma_kernel<<<mlp_blocks, 256, DSM>>>(4, 5, bs1 + H, bs2 + H,
                                             gs + H, bes + H, rms + H, rvs + H,
                                             batch, 1, n);

    head_kernel<<<GG, H>>>(lin1_W, lin1_b, lin2_W, lin2_b, out);
}

// round 6
// speedup vs baseline: 1.7800x; 1.1306x over previous
#include <cuda_runtime.h>
#include <cuda_bf16.h>
#include <cuda_fp16.h>
#include <stdint.h>

#define NN 50000
#define EE 800000
#define GG 500
#define H 128
#define OUTC 10
#define KS 136                 // padded row stride in f16 elems
#define SB 272                 // row stride bytes
#define IMG (128 * KS * 2)     // 34816 B per 128x128 f16 image
#define DSM (5 * IMG)          // 174080 B dynamic smem: A16, W1H, W1L, W2H, W2L

// ---------------- device scratch ----------------
__device__ __align__(16) __half g_hf[NN * H];   // node features (f16)
__device__ __align__(16) __half g_a16[NN * H];  // agg sums rounded to f16 (MLP input)
__device__ int   g_deg[NN];
__device__ int   g_off[NN + 1];
__device__ int   g_cursor[NN];
__device__ int   g_srcs[EE];
__device__ float g_pool[GG * H];
__device__ float g_cnt[GG];
__device__ __align__(16) __half g_wh[6 * 128 * KS];  // weight images (Wt[n][k]) f16 hi
__device__ __align__(16) __half g_wl[6 * 128 * KS];  // f16 lo (residual)

// ---------------- PTX helpers (base ISA only) ----------------
__device__ __forceinline__ uint32_t smem_u32(const void* p) {
    uint32_t a;
    asm("{ .reg .u64 t; cvta.to.shared.u64 t, %1; cvt.u32.u64 %0, t; }" : "=r"(a) : "l"(p));
    return a;
}
#define LDSM4(r0, r1, r2, r3, addr) \
    asm volatile("ldmatrix.sync.aligned.m8n8.x4.shared.b16 {%0,%1,%2,%3}, [%4];" \
                 : "=r"(r0), "=r"(r1), "=r"(r2), "=r"(r3) : "r"(addr))
#define MMA16816(d, a0, a1, a2, a3, b0, b1) \
    asm volatile("mma.sync.aligned.m16n8k16.row.col.f32.f16.f16.f32 " \
                 "{%0,%1,%2,%3}, {%4,%5,%6,%7}, {%8,%9}, {%0,%1,%2,%3};" \
                 : "+f"((d)[0]), "+f"((d)[1]), "+f"((d)[2]), "+f"((d)[3]) \
                 : "r"(a0), "r"(a1), "r"(a2), "r"(a3), "r"(b0), "r"(b1))

// ---------------- setup: zero + counts ----------------
__global__ void zero_kernel(int n) {
    int i = blockIdx.x * blockDim.x + threadIdx.x;
    if (i < n) g_deg[i] = 0;
    if (i < GG * H) g_pool[i] = 0.f;
    if (i < GG) g_cnt[i] = 0.f;
}
__global__ void count_kernel(const int* __restrict__ dst, const int* __restrict__ batch,
                             int e, int n) {
    int i = blockIdx.x * blockDim.x + threadIdx.x;
    if (i < e) atomicAdd(&g_deg[dst[i]], 1);
    if (i < n) atomicAdd(&g_cnt[batch[i]], 1.0f);
}
__global__ void scan_kernel(int n) {
    __shared__ int part[1024];
    int t = threadIdx.x;
    int chunk = (n + 1023) >> 10;
    int start = t * chunk;
    int s = 0;
    for (int i = 0; i < chunk; i++) {
        int idx = start + i;
        if (idx < n) s += g_deg[idx];
    }
    part[t] = s;
    __syncthreads();
    for (int off = 1; off < 1024; off <<= 1) {
        int v = 0;
        if (t >= off) v = part[t - off];
        __syncthreads();
        part[t] += v;
        __syncthreads();
    }
    int base = (t == 0) ? 0 : part[t - 1];
    for (int i = 0; i < chunk; i++) {
        int idx = start + i;
        if (idx < n) {
            g_off[idx] = base;
            g_cursor[idx] = base;
            base += g_deg[idx];
        }
    }
    if (t == 1023) g_off[n] = part[1023];
}
__global__ void fill_kernel(const int* __restrict__ src, const int* __restrict__ dst, int e) {
    int i = blockIdx.x * blockDim.x + threadIdx.x;
    if (i < e) {
        int d = dst[i];
        int p = atomicAdd(&g_cursor[d], 1);
        g_srcs[p] = src[i];
    }
}

// ---------------- x -> f16 convert ----------------
__global__ void xconv_kernel(const float* __restrict__ x, int total4) {
    int i = blockIdx.x * blockDim.x + threadIdx.x;
    if (i < total4) {
        float4 v = ((const float4*)x)[i];
        __half2 h0 = __floats2half2_rn(v.x, v.y);
        __half2 h1 = __floats2half2_rn(v.z, v.w);
        uint2 o;
        o.x = *(unsigned int*)&h0;
        o.y = *(unsigned int*)&h1;
        ((uint2*)g_hf)[i] = o;
    }
}

// ---------------- aggregation: f16 gather, f32 accumulate, f16 store ----------------
__global__ void agg_kernel(const float* __restrict__ eps, int n) {
    int gw = (blockIdx.x * blockDim.x + threadIdx.x) >> 5;
    int lane = threadIdx.x & 31;
    if (gw >= n) return;
    const uint2* in2 = (const uint2*)g_hf;
    float e = 1.0f + *eps;
    uint2 sv = in2[(size_t)gw * 32 + lane];
    float2 f01 = __half22float2(*(__half2*)&sv.x);
    float2 f23 = __half22float2(*(__half2*)&sv.y);
    float4 acc;
    acc.x = f01.x * e; acc.y = f01.y * e; acc.z = f23.x * e; acc.w = f23.y * e;
    int s0 = g_off[gw], s1 = g_off[gw + 1];
    int i = s0;
    for (; i + 3 < s1; i += 4) {
        uint2 va = in2[(size_t)g_srcs[i] * 32 + lane];
        uint2 vb = in2[(size_t)g_srcs[i + 1] * 32 + lane];
        uint2 vc = in2[(size_t)g_srcs[i + 2] * 32 + lane];
        uint2 vd = in2[(size_t)g_srcs[i + 3] * 32 + lane];
        float2 a01 = __half22float2(*(__half2*)&va.x);
        float2 a23 = __half22float2(*(__half2*)&va.y);
        float2 b01 = __half22float2(*(__half2*)&vb.x);
        float2 b23 = __half22float2(*(__half2*)&vb.y);
        float2 c01 = __half22float2(*(__half2*)&vc.x);
        float2 c23 = __half22float2(*(__half2*)&vc.y);
        float2 d01 = __half22float2(*(__half2*)&vd.x);
        float2 d23 = __half22float2(*(__half2*)&vd.y);
        acc.x += (a01.x + b01.x) + (c01.x + d01.x);
        acc.y += (a01.y + b01.y) + (c01.y + d01.y);
        acc.z += (a23.x + b23.x) + (c23.x + d23.x);
        acc.w += (a23.y + b23.y) + (c23.y + d23.y);
    }
    for (; i < s1; i++) {
        uint2 va = in2[(size_t)g_srcs[i] * 32 + lane];
        float2 a01 = __half22float2(*(__half2*)&va.x);
        float2 a23 = __half22float2(*(__half2*)&va.y);
        acc.x += a01.x; acc.y += a01.y; acc.z += a23.x; acc.w += a23.y;
    }
    __half2 o0 = __floats2half2_rn(acc.x, acc.y);
    __half2 o1 = __floats2half2_rn(acc.z, acc.w);
    uint2 o;
    o.x = *(unsigned int*)&o0;
    o.y = *(unsigned int*)&o1;
    ((uint2*)g_a16)[(size_t)gw * 32 + lane] = o;
}

// ---------------- weight prep: Wt[n][k] f16 hi/lo, padded stride ----------------
__global__ void wprep_kernel(const float* __restrict__ c1W1, const float* __restrict__ c1W2,
                             const float* __restrict__ Ws1, const float* __restrict__ Ws2) {
    int m = blockIdx.x >> 2;
    int rg = blockIdx.x & 3;
    const float* W;
    if (m == 0) W = c1W1;
    else if (m == 1) W = c1W2;
    else {
        int l = (m - 2) >> 1;
        W = ((m & 1) == 0) ? (Ws1 + l * H * H) : (Ws2 + l * H * H);
    }
    int tid = threadIdx.x;
    int nrow = rg * 32 + (tid >> 3);
    int kb = (tid & 7) * 16;
    __half* oh = g_wh + m * 128 * KS;
    __half* ol = g_wl + m * 128 * KS;
#pragma unroll
    for (int i = 0; i < 8; i++) {
        int k = kb + 2 * i;
        float v0 = W[k * H + nrow];
        float v1 = W[(k + 1) * H + nrow];
        __half2 h2 = __floats2half2_rn(v0, v1);
        float2 hf = __half22float2(h2);
        __half2 l2 = __floats2half2_rn(v0 - hf.x, v1 - hf.y);
        *(__half2*)(oh + nrow * KS + k) = h2;
        *(__half2*)(ol + nrow * KS + k) = l2;
    }
}

// ---------------- fused MLP on mma.sync (f16 A, f16 hi/lo W split) ----------------
__global__ __launch_bounds__(256, 1) void mlp_mma_kernel(
    int w1i, int w2i,
    const float* __restrict__ b1, const float* __restrict__ b2,
    const float* __restrict__ gam, const float* __restrict__ bet,
    const float* __restrict__ rm, const float* __restrict__ rv,
    const int* __restrict__ batchv, int lastlayer, int n) {
    extern __shared__ char dsm[];
    __shared__ float s_b1[H], s_b2[H], s_sc[H], s_sf[H];

    char* A16 = dsm;
    char* W1H = dsm + 1 * IMG;
    char* W1L = dsm + 2 * IMG;
    char* W2H = dsm + 3 * IMG;
    char* W2L = dsm + 4 * IMG;

    int tid = threadIdx.x, wid = tid >> 5, lane = tid & 31;
    int wm = wid >> 1, wn = wid & 1;        // 4x2 warp grid; warp tile 32(m) x 64(n)
    int qg = lane >> 2, qt = lane & 3;      // quad group / thread

    if (tid < H) {
        s_b1[tid] = b1[tid];
        s_b2[tid] = b2[tid];
        float sc = gam[tid] * rsqrtf(rv[tid] + 1e-5f);
        s_sc[tid] = sc;
        s_sf[tid] = bet[tid] - rm[tid] * sc;
    }
    // weight image copies (global, already split+padded)
    {
        const uint4* s1 = (const uint4*)(g_wh + w1i * 128 * KS);
        const uint4* s2 = (const uint4*)(g_wl + w1i * 128 * KS);
        const uint4* s3 = (const uint4*)(g_wh + w2i * 128 * KS);
        const uint4* s4 = (const uint4*)(g_wl + w2i * 128 * KS);
        uint4* d1 = (uint4*)W1H; uint4* d2 = (uint4*)W1L;
        uint4* d3 = (uint4*)W2H; uint4* d4 = (uint4*)W2L;
        for (int j = tid; j < IMG / 16; j += 256) {
            d1[j] = s1[j]; d2[j] = s2[j]; d3[j] = s3[j]; d4[j] = s4[j];
        }
    }
    // build A image (straight f16 copy, padded stride)
    int row0 = blockIdx.x * 128;
    {
        int r = tid >> 1, cb0 = (tid & 1) * 64;
        int grow = row0 + r;
        uint4* drow = (uint4*)(A16 + r * SB + cb0 * 2);
        if (grow < n) {
            const uint4* srow = (const uint4*)(g_a16 + (size_t)grow * H + cb0);
#pragma unroll
            for (int i = 0; i < 8; i++) drow[i] = srow[i];
        } else {
            uint4 z = make_uint4(0, 0, 0, 0);
#pragma unroll
            for (int i = 0; i < 8; i++) drow[i] = z;
        }
    }
    __syncthreads();

    // per-lane ldmatrix address offsets
    uint32_t aA16 = smem_u32(A16);
    uint32_t aW1H = smem_u32(W1H), aW1L = smem_u32(W1L);
    uint32_t aW2H = smem_u32(W2H), aW2L = smem_u32(W2L);
    uint32_t a_loff = (uint32_t)((wm * 32 + (lane & 15)) * SB + (lane >> 4) * 16);
    uint32_t b_row = (uint32_t)((lane & 7) | ((lane & 16) >> 1));
    uint32_t b_loff = (uint32_t)((wn * 64) * SB) + b_row * SB + (((uint32_t)lane >> 3) & 1) * 16;

    float acc[2][8][4];

    for (int pass = 0; pass < 2; pass++) {
        uint32_t wHI = pass ? aW2H : aW1H;
        uint32_t wLO = pass ? aW2L : aW1L;
#pragma unroll
        for (int mf = 0; mf < 2; mf++)
#pragma unroll
            for (int nf = 0; nf < 8; nf++)
#pragma unroll
                for (int q = 0; q < 4; q++) acc[mf][nf][q] = 0.f;

#pragma unroll
        for (int ks = 0; ks < 8; ks++) {
            uint32_t a0, a1, a2, a3, a4, a5, a6, a7;
            uint32_t abase = aA16 + a_loff + (uint32_t)(ks * 32);
            LDSM4(a0, a1, a2, a3, abase);
            LDSM4(a4, a5, a6, a7, abase + 16u * SB);
#pragma unroll
            for (int prod = 0; prod < 2; prod++) {
                uint32_t wb = prod ? wLO : wHI;
#pragma unroll
                for (int g2 = 0; g2 < 4; g2++) {
                    uint32_t b0, b1x, b2, b3;
                    uint32_t bbase = wb + b_loff + (uint32_t)(g2 * 16 * SB + ks * 32);
                    LDSM4(b0, b1x, b2, b3, bbase);
                    MMA16816(acc[0][2 * g2],     a0, a1, a2, a3, b0, b1x);
                    MMA16816(acc[0][2 * g2 + 1], a0, a1, a2, a3, b2, b3);
                    MMA16816(acc[1][2 * g2],     a4, a5, a6, a7, b0, b1x);
                    MMA16816(acc[1][2 * g2 + 1], a4, a5, a6, a7, b2, b3);
                }
            }
        }

        if (pass == 0) {
            // epilogue 1: bias + relu -> rebuild A image (f16)
            __syncthreads();
#pragma unroll
            for (int mf = 0; mf < 2; mf++) {
                int rA = wm * 32 + mf * 16 + qg;
#pragma unroll
                for (int nf = 0; nf < 8; nf++) {
                    int c = wn * 64 + nf * 8 + 2 * qt;
                    float v0 = fmaxf(acc[mf][nf][0] + s_b1[c], 0.f);
                    float v1 = fmaxf(acc[mf][nf][1] + s_b1[c + 1], 0.f);
                    float v2 = fmaxf(acc[mf][nf][2] + s_b1[c], 0.f);
                    float v3 = fmaxf(acc[mf][nf][3] + s_b1[c + 1], 0.f);
                    *(__half2*)(A16 + rA * SB + c * 2)       = __floats2half2_rn(v0, v1);
                    *(__half2*)(A16 + (rA + 8) * SB + c * 2) = __floats2half2_rn(v2, v3);
                }
            }
            __syncthreads();
        }
    }

    // epilogue 2: bias + relu + BN -> g_hf f16 (or atomic pool on last layer)
#pragma unroll
    for (int mf = 0; mf < 2; mf++) {
        int rA = wm * 32 + mf * 16 + qg;
        int growA = row0 + rA, growB = growA + 8;
#pragma unroll
        for (int nf = 0; nf < 8; nf++) {
            int c = wn * 64 + nf * 8 + 2 * qt;
            float o0 = fmaxf(acc[mf][nf][0] + s_b2[c], 0.f)     * s_sc[c]     + s_sf[c];
            float o1 = fmaxf(acc[mf][nf][1] + s_b2[c + 1], 0.f) * s_sc[c + 1] + s_sf[c + 1];
            float o2 = fmaxf(acc[mf][nf][2] + s_b2[c], 0.f)     * s_sc[c]     + s_sf[c];
            float o3 = fmaxf(acc[mf][nf][3] + s_b2[c + 1], 0.f) * s_sc[c + 1] + s_sf[c + 1];
            if (!lastlayer) {
                if (growA < n) *(__half2*)&g_hf[(size_t)growA * H + c] = __floats2half2_rn(o0, o1);
                if (growB < n) *(__half2*)&g_hf[(size_t)growB * H + c] = __floats2half2_rn(o2, o3);
            } else {
                if (growA < n) {
                    float* pp = g_pool + (size_t)batchv[growA] * H + c;
                    atomicAdd(pp, o0);
                    atomicAdd(pp + 1, o1);
                }
                if (growB < n) {
                    float* pp = g_pool + (size_t)batchv[growB] * H + c;
                    atomicAdd(pp, o2);
                    atomicAdd(pp + 1, o3);
                }
            }
        }
    }
}

// ---------------- head ----------------
__global__ void head_kernel(const float* __restrict__ lin1W, const float* __restrict__ lin1b,
                            const float* __restrict__ lin2W, const float* __restrict__ lin2b,
                            float* __restrict__ out) {
    __shared__ float sh[H];
    __shared__ float tt[H];
    __shared__ float lg[OUTC];
    int g = blockIdx.x, j = threadIdx.x;
    float c = g_cnt[g];
    if (c < 1.0f) c = 1.0f;
    sh[j] = g_pool[g * H + j] / c;
    __syncthreads();
    float s = lin1b[j];
#pragma unroll 8
    for (int k = 0; k < H; k++) s += sh[k] * lin1W[k * H + j];
    tt[j] = s > 0.f ? s : 0.f;
    __syncthreads();
    if (j < OUTC) {
        float s2 = lin2b[j];
#pragma unroll 8
        for (int k = 0; k < H; k++) s2 += tt[k] * lin2W[k * OUTC + j];
        lg[j] = s2;
    }
    __syncthreads();
    if (j == 0) {
        float m = lg[0];
#pragma unroll
        for (int o = 1; o < OUTC; o++) m = lg[o] > m ? lg[o] : m;
        float se = 0.f;
#pragma unroll
        for (int o = 0; o < OUTC; o++) se += expf(lg[o] - m);
        float l = m + logf(se);
#pragma unroll
        for (int o = 0; o < OUTC; o++) out[g * OUTC + o] = lg[o] - l;
    }
}

// ---------------- launch ----------------
extern "C" void kernel_launch(void* const* d_in, const int* in_sizes, int n_in,
                              void* d_out, int out_size) {
    const float* x      = (const float*)d_in[0];
    const int*   ei     = (const int*)d_in[1];
    const int*   batch  = (const int*)d_in[2];
    const float* c1_W1  = (const float*)d_in[3];
    const float* c1_b1  = (const float*)d_in[4];
    const float* c1_W2  = (const float*)d_in[5];
    const float* c1_b2  = (const float*)d_in[6];
    const float* c1_g   = (const float*)d_in[7];
    const float* c1_be  = (const float*)d_in[8];
    const float* c1_rm  = (const float*)d_in[9];
    const float* c1_rv  = (const float*)d_in[10];
    const float* c1_eps = (const float*)d_in[11];
    const float* Ws1    = (const float*)d_in[12];
    const float* bs1    = (const float*)d_in[13];
    const float* Ws2    = (const float*)d_in[14];
    const float* bs2    = (const float*)d_in[15];
    const float* gs     = (const float*)d_in[16];
    const float* bes    = (const float*)d_in[17];
    const float* rms    = (const float*)d_in[18];
    const float* rvs    = (const float*)d_in[19];
    const float* epss   = (const float*)d_in[20];
    const float* lin1_W = (const float*)d_in[21];
    const float* lin1_b = (const float*)d_in[22];
    const float* lin2_W = (const float*)d_in[23];
    const float* lin2_b = (const float*)d_in[24];
    float* out = (float*)d_out;

    int n = in_sizes[0] / H;
    int e = in_sizes[1] / 2;

    cudaFuncSetAttribute(mlp_mma_kernel, cudaFuncAttributeMaxDynamicSharedMemorySize, DSM);

    const int* src = ei;
    const int* dst = ei + e;

    // setup + CSR build
    zero_kernel<<<(GG * H + 255) / 256, 256>>>(n);
    count_kernel<<<(e + 255) / 256, 256>>>(dst, batch, e, n);
    scan_kernel<<<1, 1024>>>(n);
    fill_kernel<<<(e + 255) / 256, 256>>>(src, dst, e);
    wprep_kernel<<<24, 256>>>(c1_W1, c1_W2, Ws1, Ws2);
    xconv_kernel<<<(n * H / 4 + 255) / 256, 256>>>(x, n * H / 4);

    int agg_blocks = (n * 32 + 255) / 256;
    int mlp_blocks = (n + 127) / 128;

    // layer 1
    agg_kernel<<<agg_blocks, 256>>>(c1_eps, n);
    mlp_mma_kernel<<<mlp_blocks, 256, DSM>>>(0, 1, c1_b1, c1_b2,
                                             c1_g, c1_be, c1_rm, c1_rv,
                                             batch, 0, n);
    // layer 2
    agg_kernel<<<agg_blocks, 256>>>(epss + 0, n);
    mlp_mma_kernel<<<mlp_blocks, 256, DSM>>>(2, 3, bs1, bs2,
                                             gs, bes, rms, rvs,
                                             batch, 0, n);
    // layer 3 (pools directly)
    agg_kernel<<<agg_blocks, 256>>>(epss + 1, n);
    mlp_mma_kernel<<<mlp_blocks, 256, DSM>>>(4, 5, bs1 + H, bs2 + H,
                                             gs + H, bes + H, rms + H, rvs + H,
                                             batch, 1, n);

    head_kernel<<<GG, H>>>(lin1_W, lin1_b, lin2_W, lin2_b, out);
}